// round 12
// baseline (speedup 1.0000x reference)
#include <cuda_runtime.h>

// PointPillarScatter: out[b,c,yi,xi] = feat[b,c,n*] where n* = max point index
// mapping to cell (yi,xi) in batch b (JAX scatter-set last-wins); 0 elsewhere.
// Index math replicates XLA: /0.16f -> *fp32(1/0.16f) == *6.25f exactly.
//
// Fine-grained pipelined overlap at half-batch (8-slot) chunk granularity:
//   S0: winner || T(c0)         (winner result first needed in S1)
//   Sk: T(ck) || F(ck-1)        k = 1..7, Bresenham block interleave
//   S8: F(c7)
// Scratch = 2 x 12.8 MB ping-pong chunk buffers (L2-resident; feat read
// __ldcs, output written __stcs so the streams don't evict them).

namespace {
constexpr int B  = 4;
constexpr int C  = 64;
constexpr int N  = 100000;
constexpr int NY = 496;
constexpr int NX = 432;
constexpr int CELLS  = NY * NX;        // 214272
constexpr int VCELLS = CELLS / 4;      // 53568 (float4 granularity)
constexpr int NV     = N / 4;          // 25000 point-quads
constexpr int CSLOTS = 8;              // channel-quad slots per chunk (half batch)

constexpr int T_ITEMS = CSLOTS * NV;          // 200000
constexpr int F_ITEMS = CSLOTS * VCELLS;      // 428544
constexpr int T_BLK   = (T_ITEMS + 255) / 256;   // 782
constexpr int F_BLK   = F_ITEMS / 256;           // 1674 (exact)
constexpr int TF_BLK  = T_BLK + F_BLK;           // 2456
constexpr int W_PB    = (N + 255) / 256;         // 391 winner blocks per batch
constexpr int W_BLK   = W_PB * B;                // 1564
}

// Scratch (no runtime allocation allowed).
__device__ __align__(16) int   g_winner[B * CELLS];
__device__ float g_minxy[B][2];
__device__ __align__(16) float g_buf[2][(size_t)CSLOTS * N * 4];   // 2 x 12.8 MB

__device__ __forceinline__ void atomicMinF(float* addr, float v) {
    if (v >= 0.0f) atomicMin((int*)addr, __float_as_int(v));
    else           atomicMax((unsigned int*)addr, __float_as_uint(v));
}

__global__ void pp_init() {
    int i = blockIdx.x * blockDim.x + threadIdx.x;
    if (i < B * VCELLS) reinterpret_cast<int4*>(g_winner)[i] = make_int4(-1, -1, -1, -1);
    if (i < B * 2) reinterpret_cast<float*>(g_minxy)[i] = __int_as_float(0x7f800000);
}

// Per-batch min over x,y. points row = [b, x, y, z] as float4.
__global__ void pp_min(const float4* __restrict__ pts) {
    const int b = blockIdx.y;
    const float INF = __int_as_float(0x7f800000);
    float mx = INF, my = INF;
    for (int n = blockIdx.x * blockDim.x + threadIdx.x; n < N; n += gridDim.x * blockDim.x) {
        float4 v = pts[b * N + n];
        mx = fminf(mx, v.y);
        my = fminf(my, v.z);
    }
    #pragma unroll
    for (int o = 16; o; o >>= 1) {
        mx = fminf(mx, __shfl_xor_sync(0xffffffffu, mx, o));
        my = fminf(my, __shfl_xor_sync(0xffffffffu, my, o));
    }
    __shared__ float sx[32], sy[32];
    const int warp = threadIdx.x >> 5, lane = threadIdx.x & 31;
    if (lane == 0) { sx[warp] = mx; sy[warp] = my; }
    __syncthreads();
    if (warp == 0) {
        const int nw = blockDim.x >> 5;
        mx = (lane < nw) ? sx[lane] : INF;
        my = (lane < nw) ? sy[lane] : INF;
        #pragma unroll
        for (int o = 16; o; o >>= 1) {
            mx = fminf(mx, __shfl_xor_sync(0xffffffffu, mx, o));
            my = fminf(my, __shfl_xor_sync(0xffffffffu, my, o));
        }
        if (lane == 0) {
            atomicMinF(&g_minxy[b][0], mx);
            atomicMinF(&g_minxy[b][1], my);
        }
    }
}

// Winner role: elect per-cell winner = max point index (last-wins).
__device__ __forceinline__ void w_body(const float4* __restrict__ pts, int blk) {
    const int b = blk / W_PB;
    const int n = (blk % W_PB) * 256 + threadIdx.x;
    if (n >= N) return;
    float4 v = pts[b * N + n];
    const float R = 6.25f;                 // fp32(1/0.16f) == 6.25f (XLA rewrite)
    int xi = (int)floorf((v.y - g_minxy[b][0]) * R);
    int yi = (int)floorf((v.z - g_minxy[b][1]) * R);
    xi = min(max(xi, 0), NX - 1);
    yi = min(max(yi, 0), NY - 1);
    atomicMax(&g_winner[b * CELLS + yi * NX + xi], n);
}

// Transpose role for chunk c: feat[b][sg*4+k][n] -> buf[c&1][sl][n][k],
// sl = 0..7, sg = (c&1)*8 + sl. Fully coalesced; feat streamed (__ldcs).
__device__ __forceinline__ void t_body(const float* __restrict__ feat, int c, int blk) {
    int idx = blk * 256 + threadIdx.x;
    if (idx >= T_ITEMS) return;
    const int nv = idx % NV;
    const int sl = idx / NV;
    const int b  = c >> 1;
    const int sg = (c & 1) * CSLOTS + sl;
    const float4* base = reinterpret_cast<const float4*>(feat);
    const size_t row = ((size_t)b * C + sg * 4) * NV;
    float4 r0 = __ldcs(base + row + 0 * NV + nv);
    float4 r1 = __ldcs(base + row + 1 * NV + nv);
    float4 r2 = __ldcs(base + row + 2 * NV + nv);
    float4 r3 = __ldcs(base + row + 3 * NV + nv);
    float4* o = reinterpret_cast<float4*>(g_buf[c & 1]) + (size_t)sl * N + nv * 4;
    o[0] = make_float4(r0.x, r1.x, r2.x, r3.x);
    o[1] = make_float4(r0.y, r1.y, r2.y, r3.y);
    o[2] = make_float4(r0.z, r1.z, r2.z, r3.z);
    o[3] = make_float4(r0.w, r1.w, r2.w, r3.w);
}

// Fill role for chunk c: one 16B gather per (cell, 4ch) from the L2-resident
// chunk buffer; 4 streaming coalesced STG.128 per thread.
__device__ __forceinline__ void f_body(float4* __restrict__ out, int c, int blk) {
    int idx = blk * 256 + threadIdx.x;          // grid exact (F_ITEMS % 256 == 0)
    const int v  = idx % VCELLS;
    const int sl = idx / VCELLS;
    const int b  = c >> 1;
    const int sg = (c & 1) * CSLOTS + sl;
    int4 w = reinterpret_cast<const int4*>(g_winner)[b * VCELLS + v];
    const float4* fp = reinterpret_cast<const float4*>(g_buf[c & 1]) + (size_t)sl * N;
    const float4 z = make_float4(0.f, 0.f, 0.f, 0.f);
    float4 g0 = (w.x >= 0) ? __ldg(fp + w.x) : z;
    float4 g1 = (w.y >= 0) ? __ldg(fp + w.y) : z;
    float4 g2 = (w.z >= 0) ? __ldg(fp + w.z) : z;
    float4 g3 = (w.w >= 0) ? __ldg(fp + w.w) : z;
    float4* ob = out + ((size_t)b * C + sg * 4) * VCELLS + v;
    __stcs(ob + 0 * VCELLS, make_float4(g0.x, g1.x, g2.x, g3.x));
    __stcs(ob + 1 * VCELLS, make_float4(g0.y, g1.y, g2.y, g3.y));
    __stcs(ob + 2 * VCELLS, make_float4(g0.z, g1.z, g2.z, g3.z));
    __stcs(ob + 3 * VCELLS, make_float4(g0.w, g1.w, g2.w, g3.w));
}

// S0: winner election alongside transpose of chunk 0 (winner first used in S1).
__global__ void __launch_bounds__(256) pp_step0(const float4* __restrict__ pts,
                                                const float* __restrict__ feat) {
    const int bx = blockIdx.x;
    if (bx < W_BLK) w_body(pts, bx);
    else            t_body(feat, 0, bx - W_BLK);
}

// Middle step: T(tc) || F(tc-1), Bresenham-interleaved block roles.
__global__ void __launch_bounds__(256) pp_tf(const float* __restrict__ feat,
                                             float4* __restrict__ out, int tc) {
    const int bx = blockIdx.x;
    int tBefore = (int)(((long long)bx * T_BLK) / TF_BLK);
    int tNext   = (int)(((long long)(bx + 1) * T_BLK) / TF_BLK);
    if (tNext > tBefore) t_body(feat, tc, tBefore);
    else                 f_body(out, tc - 1, bx - tBefore);
}

// Tail: F(chunk 7).
__global__ void __launch_bounds__(256) pp_ftail(float4* __restrict__ out) {
    f_body(out, 7, blockIdx.x);
}

extern "C" void kernel_launch(void* const* d_in, const int* in_sizes, int n_in,
                              void* d_out, int out_size) {
    (void)in_sizes; (void)n_in; (void)out_size;
    const float*  feat = (const float*)d_in[0];   // (B, C, N) f32
    const float4* pts  = (const float4*)d_in[1];  // (B*N, 4)  f32
    float4* out = (float4*)d_out;
    // d_in[2] (voxel_coords) unused by the reference computation.

    pp_init<<<(B * VCELLS + 255) / 256, 256>>>();
    pp_min<<<dim3(98, B), 256>>>(pts);
    pp_step0<<<W_BLK + T_BLK, 256>>>(pts, feat);          // winner || T(c0)
    for (int c = 1; c < 8; ++c)
        pp_tf<<<TF_BLK, 256>>>(feat, out, c);             // T(c) || F(c-1)
    pp_ftail<<<F_BLK, 256>>>(out);                        // F(c7)
}

// round 13
// speedup vs baseline: 1.0911x; 1.0911x over previous
#include <cuda_runtime.h>

// PointPillarScatter: out[b,c,yi,xi] = feat[b,c,n*] where n* = max point index
// mapping to cell (yi,xi) in batch b (JAX scatter-set last-wins); 0 elsewhere.
// Index math replicates XLA: /0.16f -> *fp32(1/0.16f) == *6.25f exactly.
//
// R11 pipeline (best known: full-batch steps, 2 x 25.6 MB ping-pong scratch,
// Bresenham T/F block interleave) + fusions of the small kernels into the
// pipeline ends:
//   L0: init || min
//   L1: winner || T(b0)
//   Lk: T(bk) || F(bk-1)   k = 1..3
//   L4: F(b3)

namespace {
constexpr int B  = 4;
constexpr int C  = 64;
constexpr int N  = 100000;
constexpr int NY = 496;
constexpr int NX = 432;
constexpr int CELLS  = NY * NX;        // 214272
constexpr int VCELLS = CELLS / 4;      // 53568 (float4 granularity)
constexpr int NV     = N / 4;          // 25000 point-quads
constexpr int SLOTS  = C / 4;          // 16 channel-quad groups per batch

constexpr int T_ITEMS  = SLOTS * NV;        // 400000
constexpr int F_ITEMS  = SLOTS * VCELLS;    // 857088
constexpr int T_BLOCKS = (T_ITEMS + 255) / 256;   // 1563
constexpr int F_BLOCKS = F_ITEMS / 256;           // 3348 (exact)
constexpr int TF_BLOCKS = T_BLOCKS + F_BLOCKS;    // 4911

constexpr int I_BLOCKS = (B * VCELLS + 255) / 256;   // 837 init blocks
constexpr int M_PB     = 98;                          // min blocks per batch
constexpr int M_BLOCKS = M_PB * B;                    // 392
constexpr int W_PB     = (N + 255) / 256;             // 391 winner blocks/batch
constexpr int W_BLOCKS = W_PB * B;                    // 1564
}

// Scratch (no runtime allocation allowed).
__device__ __align__(16) int   g_winner[B * CELLS];
__device__ float g_minxy[B][2];
__device__ __align__(16) float g_buf[2][(size_t)SLOTS * N * 4];   // 2 x 25.6 MB

__device__ __forceinline__ void atomicMinF(float* addr, float v) {
    if (v >= 0.0f) atomicMin((int*)addr, __float_as_int(v));
    else           atomicMax((unsigned int*)addr, __float_as_uint(v));
}

// ── L0: init || min ──────────────────────────────────────────────────────
__device__ __forceinline__ void init_body(int blk) {
    int i = blk * 256 + threadIdx.x;
    if (i < B * VCELLS) reinterpret_cast<int4*>(g_winner)[i] = make_int4(-1, -1, -1, -1);
    if (i < B * 2) reinterpret_cast<float*>(g_minxy)[i] = __int_as_float(0x7f800000);
}

__device__ __forceinline__ void min_body(const float4* __restrict__ pts, int blk) {
    const int b = blk / M_PB;
    const int bx = blk % M_PB;
    const float INF = __int_as_float(0x7f800000);
    float mx = INF, my = INF;
    for (int n = bx * 256 + threadIdx.x; n < N; n += M_PB * 256) {
        float4 v = pts[b * N + n];
        mx = fminf(mx, v.y);
        my = fminf(my, v.z);
    }
    #pragma unroll
    for (int o = 16; o; o >>= 1) {
        mx = fminf(mx, __shfl_xor_sync(0xffffffffu, mx, o));
        my = fminf(my, __shfl_xor_sync(0xffffffffu, my, o));
    }
    __shared__ float sx[8], sy[8];
    const int warp = threadIdx.x >> 5, lane = threadIdx.x & 31;
    if (lane == 0) { sx[warp] = mx; sy[warp] = my; }
    __syncthreads();
    if (warp == 0) {
        mx = (lane < 8) ? sx[lane] : INF;
        my = (lane < 8) ? sy[lane] : INF;
        #pragma unroll
        for (int o = 4; o; o >>= 1) {
            mx = fminf(mx, __shfl_xor_sync(0xffffffffu, mx, o));
            my = fminf(my, __shfl_xor_sync(0xffffffffu, my, o));
        }
        if (lane == 0) {
            atomicMinF(&g_minxy[b][0], mx);
            atomicMinF(&g_minxy[b][1], my);
        }
    }
}

__global__ void __launch_bounds__(256) pp_initmin(const float4* __restrict__ pts) {
    const int bx = blockIdx.x;
    if (bx < I_BLOCKS) init_body(bx);
    else               min_body(pts, bx - I_BLOCKS);
}

// ── Winner role (last-wins via atomicMax on point index) ─────────────────
__device__ __forceinline__ void w_body(const float4* __restrict__ pts, int blk) {
    const int b = blk / W_PB;
    const int n = (blk % W_PB) * 256 + threadIdx.x;
    if (n >= N) return;
    float4 v = pts[b * N + n];
    const float R = 6.25f;                 // fp32(1/0.16f) == 6.25f (XLA rewrite)
    int xi = (int)floorf((v.y - g_minxy[b][0]) * R);
    int yi = (int)floorf((v.z - g_minxy[b][1]) * R);
    xi = min(max(xi, 0), NX - 1);
    yi = min(max(yi, 0), NY - 1);
    atomicMax(&g_winner[b * CELLS + yi * NX + xi], n);
}

// ── Transpose role: feat[b][slot*4+k][n] -> buf[b&1][slot][n][k] ─────────
__device__ __forceinline__ void t_body(const float* __restrict__ feat, int b, int blk) {
    int idx = blk * 256 + threadIdx.x;
    if (idx >= T_ITEMS) return;
    const int nv   = idx % NV;
    const int slot = idx / NV;
    const float4* base = reinterpret_cast<const float4*>(feat);
    const size_t row = ((size_t)b * C + slot * 4) * NV;
    float4 r0 = __ldcs(base + row + 0 * NV + nv);
    float4 r1 = __ldcs(base + row + 1 * NV + nv);
    float4 r2 = __ldcs(base + row + 2 * NV + nv);
    float4 r3 = __ldcs(base + row + 3 * NV + nv);
    float4* o = reinterpret_cast<float4*>(g_buf[b & 1]) + (size_t)slot * N + nv * 4;
    o[0] = make_float4(r0.x, r1.x, r2.x, r3.x);
    o[1] = make_float4(r0.y, r1.y, r2.y, r3.y);
    o[2] = make_float4(r0.z, r1.z, r2.z, r3.z);
    o[3] = make_float4(r0.w, r1.w, r2.w, r3.w);
}

// ── Fill role: 16B gather per (cell, 4ch) + 4 streaming STG.128 ──────────
__device__ __forceinline__ void f_body(float4* __restrict__ out, int b, int blk) {
    int idx = blk * 256 + threadIdx.x;          // grid exact (F_ITEMS % 256 == 0)
    const int v    = idx % VCELLS;
    const int slot = idx / VCELLS;
    int4 w = reinterpret_cast<const int4*>(g_winner)[b * VCELLS + v];
    const float4* fp = reinterpret_cast<const float4*>(g_buf[b & 1]) + (size_t)slot * N;
    const float4 z = make_float4(0.f, 0.f, 0.f, 0.f);
    float4 g0 = (w.x >= 0) ? __ldg(fp + w.x) : z;
    float4 g1 = (w.y >= 0) ? __ldg(fp + w.y) : z;
    float4 g2 = (w.z >= 0) ? __ldg(fp + w.z) : z;
    float4 g3 = (w.w >= 0) ? __ldg(fp + w.w) : z;
    float4* ob = out + ((size_t)b * C + slot * 4) * VCELLS + v;
    __stcs(ob + 0 * VCELLS, make_float4(g0.x, g1.x, g2.x, g3.x));
    __stcs(ob + 1 * VCELLS, make_float4(g0.y, g1.y, g2.y, g3.y));
    __stcs(ob + 2 * VCELLS, make_float4(g0.z, g1.z, g2.z, g3.z));
    __stcs(ob + 3 * VCELLS, make_float4(g0.w, g1.w, g2.w, g3.w));
}

// ── L1: winner || T(b0) ──────────────────────────────────────────────────
__global__ void __launch_bounds__(256) pp_wt0(const float4* __restrict__ pts,
                                              const float* __restrict__ feat) {
    const int bx = blockIdx.x;
    if (bx < W_BLOCKS) w_body(pts, bx);
    else               t_body(feat, 0, bx - W_BLOCKS);
}

// ── Lk: T(tb) || F(tb-1), Bresenham-interleaved roles ────────────────────
__global__ void __launch_bounds__(256) pp_tf(const float* __restrict__ feat,
                                             float4* __restrict__ out, int tb) {
    const int bx = blockIdx.x;
    int tBefore = (int)(((long long)bx * T_BLOCKS) / TF_BLOCKS);
    int tNext   = (int)(((long long)(bx + 1) * T_BLOCKS) / TF_BLOCKS);
    if (tNext > tBefore) t_body(feat, tb, tBefore);
    else                 f_body(out, tb - 1, bx - tBefore);
}

// ── L4: F(b3) ────────────────────────────────────────────────────────────
__global__ void __launch_bounds__(256) pp_ftail(float4* __restrict__ out) {
    f_body(out, 3, blockIdx.x);
}

extern "C" void kernel_launch(void* const* d_in, const int* in_sizes, int n_in,
                              void* d_out, int out_size) {
    (void)in_sizes; (void)n_in; (void)out_size;
    const float*  feat = (const float*)d_in[0];   // (B, C, N) f32
    const float4* pts  = (const float4*)d_in[1];  // (B*N, 4)  f32
    float4* out = (float4*)d_out;
    // d_in[2] (voxel_coords) unused by the reference computation.

    pp_initmin<<<I_BLOCKS + M_BLOCKS, 256>>>(pts);       // init || min
    pp_wt0<<<W_BLOCKS + T_BLOCKS, 256>>>(pts, feat);     // winner || T(b0)
    for (int b = 1; b < B; ++b)
        pp_tf<<<TF_BLOCKS, 256>>>(feat, out, b);         // T(b) || F(b-1)
    pp_ftail<<<F_BLOCKS, 256>>>(out);                    // F(b3)
}